// round 6
// baseline (speedup 1.0000x reference)
#include <cuda_runtime.h>
#include <cuda_bf16.h>
#include <stdint.h>

#define NUM_USERS 100000
#define NUM_ITEMS 50000
#define N_NODES   (NUM_USERS + NUM_ITEMS)   // 150000
#define EMBED_DIM 64
#define N_EDGES   1000000

#define SCAN_BS   1024
#define N_SCAN_BLOCKS ((N_NODES + SCAN_BS - 1) / SCAN_BS)   // 147

// ---- static device scratch (no allocation allowed) ----
__device__ int   g_deg[N_NODES];
__device__ float g_dinv[N_NODES];
__device__ int   g_off[N_NODES + 1];
__device__ int   g_bsum[N_SCAN_BLOCKS];
__device__ int2  g_csr[N_EDGES];            // {src, norm_bits}
__device__ float g_x1[N_NODES * EMBED_DIM];
__device__ float g_x2[N_NODES * EMBED_DIM];

// -------------------- setup kernels --------------------

__global__ void k_degree(const int* __restrict__ edge_index) {
    int e = blockIdx.x * blockDim.x + threadIdx.x;
    if (e < N_EDGES) atomicAdd(&g_deg[edge_index[N_EDGES + e]], 1);
}

// per-block exclusive scan of degrees; also emits dinv (deg already loaded)
__global__ void k_scan_blocks() {
    __shared__ int s[SCAN_BS];
    int tid = threadIdx.x;
    int i = blockIdx.x * SCAN_BS + tid;
    int v = (i < N_NODES) ? g_deg[i] : 0;
    if (i < N_NODES) g_dinv[i] = (v > 0) ? rsqrtf((float)v) : 0.0f;
    s[tid] = v;
    __syncthreads();
    #pragma unroll
    for (int d = 1; d < SCAN_BS; d <<= 1) {
        int t = (tid >= d) ? s[tid - d] : 0;
        __syncthreads();
        s[tid] += t;
        __syncthreads();
    }
    if (i < N_NODES) g_off[i] = s[tid] - v;   // exclusive
    if (tid == SCAN_BS - 1) g_bsum[blockIdx.x] = s[tid];
}

// single-warp shfl scan of the 147 block sums
__global__ void k_scan_aux() {
    const int CH = (N_SCAN_BLOCKS + 31) / 32;   // 5
    int lane = threadIdx.x;
    int base = lane * CH;
    int vals[CH];
    int tot = 0;
    #pragma unroll
    for (int j = 0; j < CH; j++) {
        int idx = base + j;
        int v = (idx < N_SCAN_BLOCKS) ? g_bsum[idx] : 0;
        vals[j] = tot;
        tot += v;
    }
    int run = tot;
    #pragma unroll
    for (int d = 1; d < 32; d <<= 1) {
        int t = __shfl_up_sync(0xffffffffu, run, d);
        if (lane >= d) run += t;
    }
    int excl = run - tot;
    #pragma unroll
    for (int j = 0; j < CH; j++) {
        int idx = base + j;
        if (idx < N_SCAN_BLOCKS) g_bsum[idx] = excl + vals[j];
    }
}

__global__ void k_scan_add() {
    int i = blockIdx.x * blockDim.x + threadIdx.x;
    if (i < N_NODES) g_off[i] += g_bsum[i >> 10];
}

// scatter edges into CSR-by-dst, packed {src, norm}.
// Single atomic: bump g_off[dst] itself. Afterwards g_off[node] == end offset
// (original off[node+1]) for every node, including deg-0 nodes.
__global__ void k_scatter(const int* __restrict__ edge_index) {
    int e = blockIdx.x * blockDim.x + threadIdx.x;
    if (e < N_EDGES) {
        int src = edge_index[e];
        int dst = edge_index[N_EDGES + e];
        int pos = atomicAdd(&g_off[dst], 1);
        float norm = g_dinv[src] * g_dinv[dst];
        g_csr[pos] = make_int2(src, __float_as_int(norm));
    }
}

// -------------------- propagation --------------------
// one warp per node, float2 per lane (32 lanes x 2 = 64 dims). Unrolled x4.
__device__ __forceinline__ float2 gather_node(const float2* __restrict__ xin,
                                              int beg, int end, int lane) {
    float2 sum = make_float2(0.0f, 0.0f);
    int e = beg;
    for (; e + 3 < end; e += 4) {
        int2 p0 = g_csr[e];
        int2 p1 = g_csr[e + 1];
        int2 p2 = g_csr[e + 2];
        int2 p3 = g_csr[e + 3];
        float2 v0 = xin[(size_t)p0.x * 32 + lane];
        float2 v1 = xin[(size_t)p1.x * 32 + lane];
        float2 v2 = xin[(size_t)p2.x * 32 + lane];
        float2 v3 = xin[(size_t)p3.x * 32 + lane];
        float w0 = __int_as_float(p0.y), w1 = __int_as_float(p1.y);
        float w2 = __int_as_float(p2.y), w3 = __int_as_float(p3.y);
        sum.x = fmaf(v0.x, w0, sum.x);  sum.y = fmaf(v0.y, w0, sum.y);
        sum.x = fmaf(v1.x, w1, sum.x);  sum.y = fmaf(v1.y, w1, sum.y);
        sum.x = fmaf(v2.x, w2, sum.x);  sum.y = fmaf(v2.y, w2, sum.y);
        sum.x = fmaf(v3.x, w3, sum.x);  sum.y = fmaf(v3.y, w3, sum.y);
    }
    for (; e < end; e++) {
        int2 p = g_csr[e];
        float2 v = xin[(size_t)p.x * 32 + lane];
        float w = __int_as_float(p.y);
        sum.x = fmaf(v.x, w, sum.x);
        sum.y = fmaf(v.y, w, sum.y);
    }
    return sum;
}

// shifted-offset convention: end = g_off[node], beg = node ? g_off[node-1] : 0
__global__ void __launch_bounds__(256) k_prop1(const float2* __restrict__ emb) {
    int gtid = blockIdx.x * blockDim.x + threadIdx.x;
    int node = gtid >> 5, lane = gtid & 31;
    if (node >= N_NODES) return;
    int end = g_off[node];
    int beg = node ? g_off[node - 1] : 0;
    float2 sum = gather_node(emb, beg, end, lane);
    ((float2*)g_x1)[(size_t)node * 32 + lane] = sum;
}

__global__ void __launch_bounds__(256) k_prop2() {
    int gtid = blockIdx.x * blockDim.x + threadIdx.x;
    int node = gtid >> 5, lane = gtid & 31;
    if (node >= N_NODES) return;
    int end = g_off[node];
    int beg = node ? g_off[node - 1] : 0;
    float2 sum = gather_node((const float2*)g_x1, beg, end, lane);
    ((float2*)g_x2)[(size_t)node * 32 + lane] = sum;
}

// layer 3 + epilogue: out = 0.25*(emb + l1 + l2 + A~*l2)
__global__ void __launch_bounds__(256) k_prop_last(const float2* __restrict__ emb,
                                                   float2* __restrict__ out) {
    int gtid = blockIdx.x * blockDim.x + threadIdx.x;
    int node = gtid >> 5, lane = gtid & 31;
    if (node >= N_NODES) return;
    int end = g_off[node];
    int beg = node ? g_off[node - 1] : 0;
    float2 sum = gather_node((const float2*)g_x2, beg, end, lane);

    size_t oi = (size_t)node * 32 + lane;
    float2 e0 = emb[oi];
    float2 a1 = ((const float2*)g_x1)[oi];
    float2 a2 = ((const float2*)g_x2)[oi];
    float2 o;
    o.x = 0.25f * (e0.x + a1.x + a2.x + sum.x);
    o.y = 0.25f * (e0.y + a1.y + a2.y + sum.y);
    out[oi] = o;
}

// -------------------- launch --------------------

extern "C" void kernel_launch(void* const* d_in, const int* in_sizes, int n_in,
                              void* d_out, int out_size) {
    const int*   edge_index = (const int*)d_in[0];     // int32
    const float* emb_weight = (const float*)d_in[1];
    float*       out        = (float*)d_out;

    // zero degree counters via async memset (capture-legal, no kernel launch)
    void* deg_ptr = nullptr;
    cudaGetSymbolAddress(&deg_ptr, g_deg);
    cudaMemsetAsync(deg_ptr, 0, N_NODES * sizeof(int), 0);

    const int BS = 256;
    int gn = (N_NODES + BS - 1) / BS;
    int ge = (N_EDGES + BS - 1) / BS;

    k_degree<<<ge, BS>>>(edge_index);                // launch 0
    k_scan_blocks<<<N_SCAN_BLOCKS, SCAN_BS>>>();     // launch 1
    k_scan_aux<<<1, 32>>>();                         // launch 2
    k_scan_add<<<gn, BS>>>();                        // launch 3
    k_scatter<<<ge, BS>>>(edge_index);               // launch 4

    int gp = (N_NODES * 32 + BS - 1) / BS;
    k_prop1<<<gp, BS>>>((const float2*)emb_weight);            // launch 5 (ncu lands here)
    k_prop2<<<gp, BS>>>();                                     // launch 6
    k_prop_last<<<gp, BS>>>((const float2*)emb_weight, (float2*)out); // launch 7
}

// round 7
// speedup vs baseline: 1.1375x; 1.1375x over previous
#include <cuda_runtime.h>
#include <cuda_bf16.h>
#include <stdint.h>

#define NUM_USERS 100000
#define NUM_ITEMS 50000
#define N_NODES   (NUM_USERS + NUM_ITEMS)   // 150000
#define EMBED_DIM 64
#define N_EDGES   1000000

#define SCAN_BS   1024
#define N_SCAN_BLOCKS ((N_NODES + SCAN_BS - 1) / SCAN_BS)   // 147

#define A_FLAG (1u << 30)
#define P_FLAG (1u << 31)
#define VAL_MASK 0x3FFFFFFFu

// ---- static device scratch (no allocation allowed) ----
__device__ int      g_deg[N_NODES];
__device__ float    g_dinv[N_NODES];
__device__ int      g_off[N_NODES];        // excl prefix -> end offsets after scatter
__device__ unsigned g_part[N_SCAN_BLOCKS]; // lookback state (reset each call)
__device__ int2     g_csr[N_EDGES];        // {src, norm_bits}
__device__ float    g_x1[N_NODES * EMBED_DIM];
__device__ float    g_x2[N_NODES * EMBED_DIM];

// -------------------- setup kernels --------------------

__global__ void k_degree(const int* __restrict__ edge_index) {
    int e = blockIdx.x * blockDim.x + threadIdx.x;
    if (e < N_EDGES) atomicAdd(&g_deg[edge_index[N_EDGES + e]], 1);
}

// single-pass decoupled-lookback exclusive scan of degrees; also emits dinv.
// 147 blocks x 1024 threads — all blocks resident simultaneously (<=148 SMs).
__global__ void __launch_bounds__(SCAN_BS) k_scan() {
    __shared__ int s_wt[32];
    __shared__ int s_run;

    int tid  = threadIdx.x;
    int bid  = blockIdx.x;
    int lane = tid & 31;
    int wid  = tid >> 5;
    int i    = bid * SCAN_BS + tid;

    int v = (i < N_NODES) ? g_deg[i] : 0;
    if (i < N_NODES) g_dinv[i] = (v > 0) ? rsqrtf((float)v) : 0.0f;

    // warp-level inclusive scan
    int inc = v;
    #pragma unroll
    for (int d = 1; d < 32; d <<= 1) {
        int t = __shfl_up_sync(0xffffffffu, inc, d);
        if (lane >= d) inc += t;
    }
    if (lane == 31) s_wt[wid] = inc;
    __syncthreads();

    // warp 0: scan the 32 warp totals, publish block aggregate, do lookback
    if (wid == 0) {
        int wv = s_wt[lane];
        int winc = wv;
        #pragma unroll
        for (int d = 1; d < 32; d <<= 1) {
            int t = __shfl_up_sync(0xffffffffu, winc, d);
            if (lane >= d) winc += t;
        }
        s_wt[lane] = winc;                       // inclusive scan of warp totals
        if (lane == 31)                          // publish aggregate ASAP
            atomicExch(&g_part[bid], A_FLAG | (unsigned)winc);

        // decoupled lookback (warp-parallel, 32 predecessors per round)
        int running = 0;
        int look = bid - 1;
        while (look >= 0) {
            int idx = look - lane;
            unsigned w;
            if (idx >= 0) {
                volatile unsigned* p = (volatile unsigned*)&g_part[idx];
                do { w = *p; } while ((w & (A_FLAG | P_FLAG)) == 0);
            } else {
                w = P_FLAG;                      // before array start: prefix 0
            }
            unsigned pm = __ballot_sync(0xffffffffu, (w & P_FLAG) != 0);
            int firstP = pm ? (__ffs(pm) - 1) : 32;
            int contrib = (lane <= firstP) ? (int)(w & VAL_MASK) : 0;
            #pragma unroll
            for (int d = 16; d; d >>= 1) contrib += __shfl_down_sync(0xffffffffu, contrib, d);
            contrib = __shfl_sync(0xffffffffu, contrib, 0);
            running += contrib;
            if (firstP < 32) break;
            look -= 32;
        }
        if (lane == 31)
            atomicExch(&g_part[bid], P_FLAG | (unsigned)(running + winc));
        if (lane == 0) s_run = running;
    }
    __syncthreads();

    int excl = (wid ? s_wt[wid - 1] : 0) + (inc - v) + s_run;
    if (i < N_NODES) g_off[i] = excl;
}

// scatter edges into CSR-by-dst, packed {src, norm}. Single atomic bumps
// g_off[dst] itself; afterwards g_off[node] == end offset for every node.
__global__ void k_scatter(const int* __restrict__ edge_index) {
    int e = blockIdx.x * blockDim.x + threadIdx.x;
    if (e < N_EDGES) {
        int src = edge_index[e];
        int dst = edge_index[N_EDGES + e];
        int pos = atomicAdd(&g_off[dst], 1);
        float norm = g_dinv[src] * g_dinv[dst];
        g_csr[pos] = make_int2(src, __float_as_int(norm));
    }
}

// -------------------- propagation --------------------
// one warp per node, float2 per lane (32 lanes x 2 = 64 dims). Unrolled x2.
__device__ __forceinline__ float2 gather_node(const float2* __restrict__ xin,
                                              int beg, int end, int lane) {
    float2 sum = make_float2(0.0f, 0.0f);
    int e = beg;
    for (; e + 1 < end; e += 2) {
        int2 p0 = g_csr[e];
        int2 p1 = g_csr[e + 1];
        float2 v0 = xin[(size_t)p0.x * 32 + lane];
        float2 v1 = xin[(size_t)p1.x * 32 + lane];
        float w0 = __int_as_float(p0.y);
        float w1 = __int_as_float(p1.y);
        sum.x = fmaf(v0.x, w0, sum.x);
        sum.y = fmaf(v0.y, w0, sum.y);
        sum.x = fmaf(v1.x, w1, sum.x);
        sum.y = fmaf(v1.y, w1, sum.y);
    }
    if (e < end) {
        int2 p = g_csr[e];
        float2 v = xin[(size_t)p.x * 32 + lane];
        float w = __int_as_float(p.y);
        sum.x = fmaf(v.x, w, sum.x);
        sum.y = fmaf(v.y, w, sum.y);
    }
    return sum;
}

// shifted-offset convention: end = g_off[node], beg = node ? g_off[node-1] : 0
__global__ void __launch_bounds__(256) k_prop1(const float2* __restrict__ emb) {
    int gtid = blockIdx.x * blockDim.x + threadIdx.x;
    int node = gtid >> 5, lane = gtid & 31;
    if (node >= N_NODES) return;
    int end = g_off[node];
    int beg = node ? g_off[node - 1] : 0;
    float2 sum = gather_node(emb, beg, end, lane);
    ((float2*)g_x1)[(size_t)node * 32 + lane] = sum;
}

__global__ void __launch_bounds__(256) k_prop2() {
    int gtid = blockIdx.x * blockDim.x + threadIdx.x;
    int node = gtid >> 5, lane = gtid & 31;
    if (node >= N_NODES) return;
    int end = g_off[node];
    int beg = node ? g_off[node - 1] : 0;
    float2 sum = gather_node((const float2*)g_x1, beg, end, lane);
    ((float2*)g_x2)[(size_t)node * 32 + lane] = sum;
}

// layer 3 + epilogue: out = 0.25*(emb + l1 + l2 + A~*l2)
__global__ void __launch_bounds__(256) k_prop_last(const float2* __restrict__ emb,
                                                   float2* __restrict__ out) {
    int gtid = blockIdx.x * blockDim.x + threadIdx.x;
    int node = gtid >> 5, lane = gtid & 31;
    if (node >= N_NODES) return;
    int end = g_off[node];
    int beg = node ? g_off[node - 1] : 0;
    float2 sum = gather_node((const float2*)g_x2, beg, end, lane);

    size_t oi = (size_t)node * 32 + lane;
    float2 e0 = emb[oi];
    float2 a1 = ((const float2*)g_x1)[oi];
    float2 a2 = ((const float2*)g_x2)[oi];
    float2 o;
    o.x = 0.25f * (e0.x + a1.x + a2.x + sum.x);
    o.y = 0.25f * (e0.y + a1.y + a2.y + sum.y);
    out[oi] = o;
}

// -------------------- launch --------------------

extern "C" void kernel_launch(void* const* d_in, const int* in_sizes, int n_in,
                              void* d_out, int out_size) {
    const int*   edge_index = (const int*)d_in[0];     // int32
    const float* emb_weight = (const float*)d_in[1];
    float*       out        = (float*)d_out;

    // reset counters via async memsets (capture-legal, don't shift ncu's skip)
    void* deg_ptr = nullptr;  cudaGetSymbolAddress(&deg_ptr, g_deg);
    void* part_ptr = nullptr; cudaGetSymbolAddress(&part_ptr, g_part);
    cudaMemsetAsync(deg_ptr, 0, N_NODES * sizeof(int), 0);
    cudaMemsetAsync(part_ptr, 0, N_SCAN_BLOCKS * sizeof(unsigned), 0);

    const int BS = 256;
    int ge = (N_EDGES + BS - 1) / BS;

    k_degree<<<ge, BS>>>(edge_index);                // kernel 1
    k_scan<<<N_SCAN_BLOCKS, SCAN_BS>>>();            // kernel 2 (lookback scan)
    k_scatter<<<ge, BS>>>(edge_index);               // kernel 3

    int gp = (N_NODES * 32 + BS - 1) / BS;
    k_prop1<<<gp, BS>>>((const float2*)emb_weight);            // kernel 4 <- ncu
    k_prop2<<<gp, BS>>>();                                     // kernel 5
    k_prop_last<<<gp, BS>>>((const float2*)emb_weight, (float2*)out); // kernel 6
}

// round 8
// speedup vs baseline: 1.1810x; 1.0382x over previous
#include <cuda_runtime.h>
#include <cuda_bf16.h>
#include <stdint.h>

#define NUM_USERS 100000
#define NUM_ITEMS 50000
#define N_NODES   (NUM_USERS + NUM_ITEMS)   // 150000
#define EMBED_DIM 64
#define N_EDGES   1000000

#define SCAN_BS   1024
#define N_SCAN_BLOCKS ((N_NODES + SCAN_BS - 1) / SCAN_BS)   // 147

#define A_FLAG (1u << 30)
#define P_FLAG (1u << 31)
#define VAL_MASK 0x3FFFFFFFu

// ---- static device scratch (no allocation allowed) ----
__device__ int      g_deg[N_NODES];
__device__ float    g_dinv[N_NODES];
__device__ int      g_off[N_NODES];        // excl prefix -> end offsets after scatter
__device__ unsigned g_part[N_SCAN_BLOCKS]; // lookback state (reset each call)
__device__ int2     g_csr[N_EDGES];        // {src, norm_bits}
__device__ float    g_x1[N_NODES * EMBED_DIM];
__device__ float    g_x2[N_NODES * EMBED_DIM];

// -------------------- setup kernels --------------------

__global__ void k_degree(const int* __restrict__ edge_index) {
    int e = blockIdx.x * blockDim.x + threadIdx.x;
    if (e < N_EDGES) atomicAdd(&g_deg[edge_index[N_EDGES + e]], 1);
}

// single-pass decoupled-lookback exclusive scan of degrees; also emits dinv.
__global__ void __launch_bounds__(SCAN_BS) k_scan() {
    __shared__ int s_wt[32];
    __shared__ int s_run;

    int tid  = threadIdx.x;
    int bid  = blockIdx.x;
    int lane = tid & 31;
    int wid  = tid >> 5;
    int i    = bid * SCAN_BS + tid;

    int v = (i < N_NODES) ? g_deg[i] : 0;
    if (i < N_NODES) g_dinv[i] = (v > 0) ? rsqrtf((float)v) : 0.0f;

    int inc = v;
    #pragma unroll
    for (int d = 1; d < 32; d <<= 1) {
        int t = __shfl_up_sync(0xffffffffu, inc, d);
        if (lane >= d) inc += t;
    }
    if (lane == 31) s_wt[wid] = inc;
    __syncthreads();

    if (wid == 0) {
        int wv = s_wt[lane];
        int winc = wv;
        #pragma unroll
        for (int d = 1; d < 32; d <<= 1) {
            int t = __shfl_up_sync(0xffffffffu, winc, d);
            if (lane >= d) winc += t;
        }
        s_wt[lane] = winc;
        if (lane == 31)
            atomicExch(&g_part[bid], A_FLAG | (unsigned)winc);

        int running = 0;
        int look = bid - 1;
        while (look >= 0) {
            int idx = look - lane;
            unsigned w;
            if (idx >= 0) {
                volatile unsigned* p = (volatile unsigned*)&g_part[idx];
                do { w = *p; } while ((w & (A_FLAG | P_FLAG)) == 0);
            } else {
                w = P_FLAG;
            }
            unsigned pm = __ballot_sync(0xffffffffu, (w & P_FLAG) != 0);
            int firstP = pm ? (__ffs(pm) - 1) : 32;
            int contrib = (lane <= firstP) ? (int)(w & VAL_MASK) : 0;
            #pragma unroll
            for (int d = 16; d; d >>= 1) contrib += __shfl_down_sync(0xffffffffu, contrib, d);
            contrib = __shfl_sync(0xffffffffu, contrib, 0);
            running += contrib;
            if (firstP < 32) break;
            look -= 32;
        }
        if (lane == 31)
            atomicExch(&g_part[bid], P_FLAG | (unsigned)(running + winc));
        if (lane == 0) s_run = running;
    }
    __syncthreads();

    int excl = (wid ? s_wt[wid - 1] : 0) + (inc - v) + s_run;
    if (i < N_NODES) g_off[i] = excl;
}

// scatter edges into CSR-by-dst; single atomic bumps g_off[dst] itself.
__global__ void k_scatter(const int* __restrict__ edge_index) {
    int e = blockIdx.x * blockDim.x + threadIdx.x;
    if (e < N_EDGES) {
        int src = edge_index[e];
        int dst = edge_index[N_EDGES + e];
        int pos = atomicAdd(&g_off[dst], 1);
        float norm = g_dinv[src] * g_dinv[dst];
        g_csr[pos] = make_int2(src, __float_as_int(norm));
    }
}

// -------------------- propagation --------------------
// 2 nodes per warp: 16 lanes per node, float4 per lane (16 x 16B = 256B row).
// Each LDG.128 fetches two independent rows (one per half-warp) -> 2x MLP.
__device__ __forceinline__ float4 gather_node4(const float4* __restrict__ xin,
                                               int beg, int end, int qlane) {
    float4 sum = make_float4(0.0f, 0.0f, 0.0f, 0.0f);
    int e = beg;
    for (; e + 1 < end; e += 2) {
        int2 p0 = g_csr[e];
        int2 p1 = g_csr[e + 1];
        float4 v0 = xin[(size_t)p0.x * 16 + qlane];
        float4 v1 = xin[(size_t)p1.x * 16 + qlane];
        float w0 = __int_as_float(p0.y);
        float w1 = __int_as_float(p1.y);
        sum.x = fmaf(v0.x, w0, sum.x);  sum.y = fmaf(v0.y, w0, sum.y);
        sum.z = fmaf(v0.z, w0, sum.z);  sum.w = fmaf(v0.w, w0, sum.w);
        sum.x = fmaf(v1.x, w1, sum.x);  sum.y = fmaf(v1.y, w1, sum.y);
        sum.z = fmaf(v1.z, w1, sum.z);  sum.w = fmaf(v1.w, w1, sum.w);
    }
    if (e < end) {
        int2 p = g_csr[e];
        float4 v = xin[(size_t)p.x * 16 + qlane];
        float w = __int_as_float(p.y);
        sum.x = fmaf(v.x, w, sum.x);  sum.y = fmaf(v.y, w, sum.y);
        sum.z = fmaf(v.z, w, sum.z);  sum.w = fmaf(v.w, w, sum.w);
    }
    return sum;
}

// shifted-offset convention: end = g_off[node], beg = node ? g_off[node-1] : 0
__global__ void __launch_bounds__(256) k_prop1(const float4* __restrict__ emb) {
    int gtid = blockIdx.x * blockDim.x + threadIdx.x;
    int node = gtid >> 4, qlane = gtid & 15;
    if (node >= N_NODES) return;
    int end = g_off[node];
    int beg = node ? g_off[node - 1] : 0;
    float4 sum = gather_node4(emb, beg, end, qlane);
    ((float4*)g_x1)[(size_t)node * 16 + qlane] = sum;
}

__global__ void __launch_bounds__(256) k_prop2() {
    int gtid = blockIdx.x * blockDim.x + threadIdx.x;
    int node = gtid >> 4, qlane = gtid & 15;
    if (node >= N_NODES) return;
    int end = g_off[node];
    int beg = node ? g_off[node - 1] : 0;
    float4 sum = gather_node4((const float4*)g_x1, beg, end, qlane);
    ((float4*)g_x2)[(size_t)node * 16 + qlane] = sum;
}

// layer 3 + epilogue: out = 0.25*(emb + l1 + l2 + A~*l2)
__global__ void __launch_bounds__(256) k_prop_last(const float4* __restrict__ emb,
                                                   float4* __restrict__ out) {
    int gtid = blockIdx.x * blockDim.x + threadIdx.x;
    int node = gtid >> 4, qlane = gtid & 15;
    if (node >= N_NODES) return;
    int end = g_off[node];
    int beg = node ? g_off[node - 1] : 0;
    float4 sum = gather_node4((const float4*)g_x2, beg, end, qlane);

    size_t oi = (size_t)node * 16 + qlane;
    float4 e0 = emb[oi];
    float4 a1 = ((const float4*)g_x1)[oi];
    float4 a2 = ((const float4*)g_x2)[oi];
    float4 o;
    o.x = 0.25f * (e0.x + a1.x + a2.x + sum.x);
    o.y = 0.25f * (e0.y + a1.y + a2.y + sum.y);
    o.z = 0.25f * (e0.z + a1.z + a2.z + sum.z);
    o.w = 0.25f * (e0.w + a1.w + a2.w + sum.w);
    out[oi] = o;
}

// -------------------- launch --------------------

extern "C" void kernel_launch(void* const* d_in, const int* in_sizes, int n_in,
                              void* d_out, int out_size) {
    const int*   edge_index = (const int*)d_in[0];     // int32
    const float* emb_weight = (const float*)d_in[1];
    float*       out        = (float*)d_out;

    void* deg_ptr = nullptr;  cudaGetSymbolAddress(&deg_ptr, g_deg);
    void* part_ptr = nullptr; cudaGetSymbolAddress(&part_ptr, g_part);
    cudaMemsetAsync(deg_ptr, 0, N_NODES * sizeof(int), 0);
    cudaMemsetAsync(part_ptr, 0, N_SCAN_BLOCKS * sizeof(unsigned), 0);

    const int BS = 256;
    int ge = (N_EDGES + BS - 1) / BS;

    k_degree<<<ge, BS>>>(edge_index);                // kernel 1
    k_scan<<<N_SCAN_BLOCKS, SCAN_BS>>>();            // kernel 2
    k_scatter<<<ge, BS>>>(edge_index);               // kernel 3

    int gp = (N_NODES * 16 + BS - 1) / BS;           // 16 threads per node now
    k_prop1<<<gp, BS>>>((const float4*)emb_weight);            // kernel 4 <- ncu
    k_prop2<<<gp, BS>>>();                                     // kernel 5
    k_prop_last<<<gp, BS>>>((const float4*)emb_weight, (float4*)out); // kernel 6
}

// round 9
// speedup vs baseline: 1.4402x; 1.2195x over previous
#include <cuda_runtime.h>
#include <cuda_bf16.h>
#include <stdint.h>

#define NUM_USERS 100000
#define NUM_ITEMS 50000
#define N_NODES   (NUM_USERS + NUM_ITEMS)   // 150000
#define EMBED_DIM 64
#define N_EDGES   1000000

#define SCAN_BS   1024
#define N_SCAN_BLOCKS ((N_NODES + SCAN_BS - 1) / SCAN_BS)   // 147

#define A_FLAG (1u << 30)
#define P_FLAG (1u << 31)
#define VAL_MASK 0x3FFFFFFFu

// ---- static device scratch (no allocation allowed) ----
__device__ int      g_deg[N_NODES];
__device__ float    g_dinv[N_NODES];
__device__ int      g_off[N_NODES];        // excl prefix -> end offsets after scatter
__device__ unsigned g_part[N_SCAN_BLOCKS]; // lookback state (reset each call)
__device__ int2     g_csr[N_EDGES];        // {src, norm_bits}
__device__ float    g_x1[N_NODES * EMBED_DIM];
__device__ float    g_x2[N_NODES * EMBED_DIM];

// -------------------- setup kernels --------------------

__global__ void k_degree(const int* __restrict__ edge_index) {
    int e = blockIdx.x * blockDim.x + threadIdx.x;
    if (e < N_EDGES) atomicAdd(&g_deg[edge_index[N_EDGES + e]], 1);
}

// single-pass decoupled-lookback exclusive scan of degrees; also emits dinv.
__global__ void __launch_bounds__(SCAN_BS) k_scan() {
    __shared__ int s_wt[32];
    __shared__ int s_run;

    int tid  = threadIdx.x;
    int bid  = blockIdx.x;
    int lane = tid & 31;
    int wid  = tid >> 5;
    int i    = bid * SCAN_BS + tid;

    int v = (i < N_NODES) ? g_deg[i] : 0;
    if (i < N_NODES) g_dinv[i] = (v > 0) ? rsqrtf((float)v) : 0.0f;

    int inc = v;
    #pragma unroll
    for (int d = 1; d < 32; d <<= 1) {
        int t = __shfl_up_sync(0xffffffffu, inc, d);
        if (lane >= d) inc += t;
    }
    if (lane == 31) s_wt[wid] = inc;
    __syncthreads();

    if (wid == 0) {
        int wv = s_wt[lane];
        int winc = wv;
        #pragma unroll
        for (int d = 1; d < 32; d <<= 1) {
            int t = __shfl_up_sync(0xffffffffu, winc, d);
            if (lane >= d) winc += t;
        }
        s_wt[lane] = winc;
        if (lane == 31)
            atomicExch(&g_part[bid], A_FLAG | (unsigned)winc);

        int running = 0;
        int look = bid - 1;
        while (look >= 0) {
            int idx = look - lane;
            unsigned w;
            if (idx >= 0) {
                volatile unsigned* p = (volatile unsigned*)&g_part[idx];
                do { w = *p; } while ((w & (A_FLAG | P_FLAG)) == 0);
            } else {
                w = P_FLAG;
            }
            unsigned pm = __ballot_sync(0xffffffffu, (w & P_FLAG) != 0);
            int firstP = pm ? (__ffs(pm) - 1) : 32;
            int contrib = (lane <= firstP) ? (int)(w & VAL_MASK) : 0;
            #pragma unroll
            for (int d = 16; d; d >>= 1) contrib += __shfl_down_sync(0xffffffffu, contrib, d);
            contrib = __shfl_sync(0xffffffffu, contrib, 0);
            running += contrib;
            if (firstP < 32) break;
            look -= 32;
        }
        if (lane == 31)
            atomicExch(&g_part[bid], P_FLAG | (unsigned)(running + winc));
        if (lane == 0) s_run = running;
    }
    __syncthreads();

    int excl = (wid ? s_wt[wid - 1] : 0) + (inc - v) + s_run;
    if (i < N_NODES) g_off[i] = excl;
}

// scatter edges into CSR-by-dst; single atomic bumps g_off[dst] itself.
__global__ void k_scatter(const int* __restrict__ edge_index) {
    int e = blockIdx.x * blockDim.x + threadIdx.x;
    if (e < N_EDGES) {
        int src = edge_index[e];
        int dst = edge_index[N_EDGES + e];
        int pos = atomicAdd(&g_off[dst], 1);
        float norm = g_dinv[src] * g_dinv[dst];
        g_csr[pos] = make_int2(src, __float_as_int(norm));
    }
}

// -------------------- propagation --------------------
// 2 nodes per warp: 16 lanes per node, float4 per lane (16 x 16B = 256B row).
// Branchless batches of 4 edges: out-of-range slots clamp index to end-1
// (in-bounds load, no data dependency) and zero the weight. Always 4 gathers
// in flight per half-warp, no serial remainder.
__device__ __forceinline__ float4 gather_node4(const float4* __restrict__ xin,
                                               int beg, int end, int qlane) {
    float4 sum = make_float4(0.0f, 0.0f, 0.0f, 0.0f);
    int last = end - 1;
    for (int e = beg; e < end; e += 4) {
        int i1 = min(e + 1, last);
        int i2 = min(e + 2, last);
        int i3 = min(e + 3, last);
        int2 p0 = g_csr[e];
        int2 p1 = g_csr[i1];
        int2 p2 = g_csr[i2];
        int2 p3 = g_csr[i3];
        float4 v0 = xin[(size_t)p0.x * 16 + qlane];
        float4 v1 = xin[(size_t)p1.x * 16 + qlane];
        float4 v2 = xin[(size_t)p2.x * 16 + qlane];
        float4 v3 = xin[(size_t)p3.x * 16 + qlane];
        float w0 = __int_as_float(p0.y);
        float w1 = (e + 1 < end) ? __int_as_float(p1.y) : 0.0f;
        float w2 = (e + 2 < end) ? __int_as_float(p2.y) : 0.0f;
        float w3 = (e + 3 < end) ? __int_as_float(p3.y) : 0.0f;
        sum.x = fmaf(v0.x, w0, sum.x);  sum.y = fmaf(v0.y, w0, sum.y);
        sum.z = fmaf(v0.z, w0, sum.z);  sum.w = fmaf(v0.w, w0, sum.w);
        sum.x = fmaf(v1.x, w1, sum.x);  sum.y = fmaf(v1.y, w1, sum.y);
        sum.z = fmaf(v1.z, w1, sum.z);  sum.w = fmaf(v1.w, w1, sum.w);
        sum.x = fmaf(v2.x, w2, sum.x);  sum.y = fmaf(v2.y, w2, sum.y);
        sum.z = fmaf(v2.z, w2, sum.z);  sum.w = fmaf(v2.w, w2, sum.w);
        sum.x = fmaf(v3.x, w3, sum.x);  sum.y = fmaf(v3.y, w3, sum.y);
        sum.z = fmaf(v3.z, w3, sum.z);  sum.w = fmaf(v3.w, w3, sum.w);
    }
    return sum;
}

// shifted-offset convention: end = g_off[node], beg = node ? g_off[node-1] : 0
__global__ void __launch_bounds__(256, 7) k_prop1(const float4* __restrict__ emb) {
    int gtid = blockIdx.x * blockDim.x + threadIdx.x;
    int node = gtid >> 4, qlane = gtid & 15;
    if (node >= N_NODES) return;
    int end = g_off[node];
    int beg = node ? g_off[node - 1] : 0;
    float4 sum = gather_node4(emb, beg, end, qlane);
    ((float4*)g_x1)[(size_t)node * 16 + qlane] = sum;
}

__global__ void __launch_bounds__(256, 7) k_prop2() {
    int gtid = blockIdx.x * blockDim.x + threadIdx.x;
    int node = gtid >> 4, qlane = gtid & 15;
    if (node >= N_NODES) return;
    int end = g_off[node];
    int beg = node ? g_off[node - 1] : 0;
    float4 sum = gather_node4((const float4*)g_x1, beg, end, qlane);
    ((float4*)g_x2)[(size_t)node * 16 + qlane] = sum;
}

// layer 3 + epilogue: out = 0.25*(emb + l1 + l2 + A~*l2)
__global__ void __launch_bounds__(256, 7) k_prop_last(const float4* __restrict__ emb,
                                                      float4* __restrict__ out) {
    int gtid = blockIdx.x * blockDim.x + threadIdx.x;
    int node = gtid >> 4, qlane = gtid & 15;
    if (node >= N_NODES) return;
    int end = g_off[node];
    int beg = node ? g_off[node - 1] : 0;
    float4 sum = gather_node4((const float4*)g_x2, beg, end, qlane);

    size_t oi = (size_t)node * 16 + qlane;
    float4 e0 = emb[oi];
    float4 a1 = ((const float4*)g_x1)[oi];
    float4 a2 = ((const float4*)g_x2)[oi];
    float4 o;
    o.x = 0.25f * (e0.x + a1.x + a2.x + sum.x);
    o.y = 0.25f * (e0.y + a1.y + a2.y + sum.y);
    o.z = 0.25f * (e0.z + a1.z + a2.z + sum.z);
    o.w = 0.25f * (e0.w + a1.w + a2.w + sum.w);
    out[oi] = o;
}

// -------------------- launch --------------------

extern "C" void kernel_launch(void* const* d_in, const int* in_sizes, int n_in,
                              void* d_out, int out_size) {
    const int*   edge_index = (const int*)d_in[0];     // int32
    const float* emb_weight = (const float*)d_in[1];
    float*       out        = (float*)d_out;

    void* deg_ptr = nullptr;  cudaGetSymbolAddress(&deg_ptr, g_deg);
    void* part_ptr = nullptr; cudaGetSymbolAddress(&part_ptr, g_part);
    cudaMemsetAsync(deg_ptr, 0, N_NODES * sizeof(int), 0);
    cudaMemsetAsync(part_ptr, 0, N_SCAN_BLOCKS * sizeof(unsigned), 0);

    const int BS = 256;
    int ge = (N_EDGES + BS - 1) / BS;

    k_degree<<<ge, BS>>>(edge_index);                // kernel 1
    k_scan<<<N_SCAN_BLOCKS, SCAN_BS>>>();            // kernel 2
    k_scatter<<<ge, BS>>>(edge_index);               // kernel 3

    int gp = (N_NODES * 16 + BS - 1) / BS;           // 16 threads per node
    k_prop1<<<gp, BS>>>((const float4*)emb_weight);            // kernel 4 <- ncu
    k_prop2<<<gp, BS>>>();                                     // kernel 5
    k_prop_last<<<gp, BS>>>((const float4*)emb_weight, (float4*)out); // kernel 6
}